// round 12
// baseline (speedup 1.0000x reference)
#include <cuda_runtime.h>
#include <cuda_bf16.h>
#include <cstdint>

#define DD 16
#define LL 6
#define KK 64
#define BLOCK 256
#define TILE_M 256

typedef unsigned long long u64;
typedef unsigned int u32;

#define C1_        (-7.2134752044448169f)   /* -5 * log2(e)          */
#define C2SCALE_   (-14.426950408889634f)   /* -10 * log2(e)         */
#define PI_        3.14159265358979323846f
#define HALF_PI_   1.5707963267948966f
#define LN2_TENTH  0.069314718055994531f    /* 0.1 * ln(2)           */
#define CLIP_      0.99999994f              /* fp32(1.0 - 1e-7)      */

// B operand: [384 comps][16 u32]; row = [mh(8) | ml(8)] bf16-pairs
__device__ u32   g_B[LL * KK][16];
__device__ float g_c2p[LL * KK];   // folded: C2SCALE*alpha + C1*(pi/2)^2
__device__ float g_wv[LL];

__device__ __forceinline__ u32 pack_bf16x2(float a, float b) {
    __nv_bfloat162 h = __floats2bfloat162_rn(a, b);
    return *reinterpret_cast<u32*>(&h);
}

// ------------------------------------------------------------------ prep
__global__ void prep_kernel(const float* __restrict__ mus,
                            const float* __restrict__ alphas,
                            const float* __restrict__ ws) {
    int tid = threadIdx.x;
    if (tid < LL) {
        float w = ws[tid];
        g_wv[tid] = expf(-w * w);
    }
    if (tid >= LL * KK) return;
    int l = tid >> 6;
    int k = tid & 63;
    const float* m = mus + l * DD * KK + k;   // [L, D, K]
    float v[DD];
    float s = 0.f;
#pragma unroll
    for (int d = 0; d < DD; d++) {
        v[d] = m[d * KK];
        s += v[d] * v[d];
    }
    float inv = 1.0f / sqrtf(s);
#pragma unroll
    for (int d = 0; d < DD; d++) v[d] *= inv;
#pragma unroll
    for (int i = 0; i < 8; i++) {
        float a = v[2 * i], b = v[2 * i + 1];
        __nv_bfloat162 hb = __floats2bfloat162_rn(a, b);
        float ra = a - __bfloat162float(hb.x);
        float rb = b - __bfloat162float(hb.y);
        g_B[tid][i]     = *reinterpret_cast<u32*>(&hb);  // mh pairs
        g_B[tid][8 + i] = pack_bf16x2(ra, rb);           // ml pairs
    }
    g_c2p[tid] = C2SCALE_ * alphas[tid] + C1_ * (HALF_PI_ * HALF_PI_);
}

// ---------------------------------------------------------------- helpers
__device__ __forceinline__ float fast_sqrt(float x) {
    float r; asm("sqrt.approx.f32 %0, %1;" : "=f"(r) : "f"(x)); return r;
}
__device__ __forceinline__ float fast_ex2(float x) {
    float r; asm("ex2.approx.f32 %0, %1;" : "=f"(r) : "f"(x)); return r;
}
__device__ __forceinline__ float fast_lg2(float x) {
    float r; asm("lg2.approx.f32 %0, %1;" : "=f"(r) : "f"(x)); return r;
}
__device__ __forceinline__ u64 fma2(u64 a, u64 b, u64 c) {
    u64 d; asm("fma.rn.f32x2 %0, %1, %2, %3;" : "=l"(d) : "l"(a), "l"(b), "l"(c)); return d;
}
__device__ __forceinline__ u64 pack2(float lo, float hi) {
    u64 d; asm("mov.b64 %0, {%1, %2};" : "=l"(d) : "f"(lo), "f"(hi)); return d;
}
__device__ __forceinline__ void unpack2(u64 v, float& lo, float& hi) {
    asm("mov.b64 {%0, %1}, %2;" : "=f"(lo), "=f"(hi) : "l"(v));
}

// m16n8k16 row.col bf16 -> f32 accumulate (plain PTX, valid on compute_103)
__device__ __forceinline__ void mma16816(float& d0, float& d1, float& d2, float& d3,
                                         u32 a0, u32 a1, u32 a2, u32 a3,
                                         u32 b0, u32 b1) {
    asm volatile(
        "mma.sync.aligned.m16n8k16.row.col.f32.bf16.bf16.f32 "
        "{%0,%1,%2,%3}, {%4,%5,%6,%7}, {%8,%9}, {%0,%1,%2,%3};"
        : "+f"(d0), "+f"(d1), "+f"(d2), "+f"(d3)
        : "r"(a0), "r"(a1), "r"(a2), "r"(a3), "r"(b0), "r"(b1));
}

// ------------------------------------------------------------------ main
__global__ __launch_bounds__(BLOCK, 4)
void main_kernel(const float* __restrict__ xs,
                 float* __restrict__ out,
                 int n_total) {
    __shared__ u32    sA[TILE_M][17];   // 17.0 KB: [xh(8)|xl(8)] + pad
    __shared__ u32    sB[LL * KK][17];  // 25.5 KB: [mh(8)|ml(8)] + pad
    __shared__ float2 sC2[LL * 32];     // 1.5 KB folded c2' pairs
    __shared__ float  sWV[LL];

    const int tid = threadIdx.x;
    {
        const float2* gc = reinterpret_cast<const float2*>(g_c2p);
        for (int i = tid; i < LL * 32; i += BLOCK) sC2[i] = gc[i];
        if (tid < LL) sWV[tid] = g_wv[tid];
    }

    // ---- copy B table to smem (one-time, uint4 gmem loads) ----
    {
        const uint4* gb = reinterpret_cast<const uint4*>(&g_B[0][0]);
#pragma unroll
        for (int i = tid; i < LL * KK * 4; i += BLOCK) {   // 1536 uint4
            uint4 v = gb[i];
            int row = i >> 2;
            int w = (i & 3) * 4;
            sB[row][w]     = v.x;
            sB[row][w + 1] = v.y;
            sB[row][w + 2] = v.z;
            sB[row][w + 3] = v.w;
        }
    }

    // ---- build A rows: thread tid owns point blockIdx*256 + tid ----
    int n0 = blockIdx.x * TILE_M + tid;
    int n_c = (n0 < n_total) ? n0 : (n_total - 1);
    {
        const float4* xv = reinterpret_cast<const float4*>(xs + (size_t)n_c * DD);
        float4 v0 = xv[0], v1 = xv[1], v2 = xv[2], v3 = xv[3];
        float x[16] = {v0.x, v0.y, v0.z, v0.w, v1.x, v1.y, v1.z, v1.w,
                       v2.x, v2.y, v2.z, v2.w, v3.x, v3.y, v3.z, v3.w};
#pragma unroll
        for (int i = 0; i < 8; i++) {
            float a = x[2 * i], b = x[2 * i + 1];
            __nv_bfloat162 hb = __floats2bfloat162_rn(a, b);
            float ra = a - __bfloat162float(hb.x);
            float rb = b - __bfloat162float(hb.y);
            sA[tid][i]     = *reinterpret_cast<u32*>(&hb);
            sA[tid][8 + i] = pack_bf16x2(ra, rb);
        }
    }
    __syncthreads();

    const int wid = tid >> 5;
    const int lane = tid & 31;
    const int gid = lane >> 2;   // quad row id 0..7
    const int tig = lane & 3;    // thread-in-group

    // packed acos minimax constants (duplicated lanes)
    const u64 P7 = pack2(-0.0012624911f, -0.0012624911f);
    const u64 P6 = pack2( 0.0066700901f,  0.0066700901f);
    const u64 P5 = pack2(-0.0170881256f, -0.0170881256f);
    const u64 P4 = pack2( 0.0308918810f,  0.0308918810f);
    const u64 P3 = pack2(-0.0501743046f, -0.0501743046f);
    const u64 P2 = pack2( 0.0889789874f,  0.0889789874f);
    const u64 P1 = pack2(-0.2145988016f, -0.2145988016f);
    const u64 P0 = pack2( 1.5707963050f,  1.5707963050f);
    const float Bc = -(C1_) * PI_;

    // mt OUTER loop: only one m-tile's state live at a time (reg diet -> 4 CTAs/SM)
#pragma unroll 1
    for (int mt = 0; mt < 2; mt++) {
        const int r0 = wid * 32 + mt * 16 + gid;
        u32 ah0 = sA[r0][tig],     ah1 = sA[r0 + 8][tig];
        u32 ah2 = sA[r0][tig + 4], ah3 = sA[r0 + 8][tig + 4];
        u32 al0 = sA[r0][8 + tig],     al1 = sA[r0 + 8][8 + tig];
        u32 al2 = sA[r0][8 + tig + 4], al3 = sA[r0 + 8][8 + tig + 4];

        float F0 = 0.f, F1 = 0.f;
#pragma unroll 1
        for (int l = 0; l < LL; l++) {
            float sum0 = 0.f, sum1 = 0.f;
#pragma unroll
            for (int nt = 0; nt < 8; nt++) {
                const int comp = l * 64 + nt * 8 + gid;
                u32 bh0 = sB[comp][tig];
                u32 bh1 = sB[comp][tig + 4];
                u32 bl0 = sB[comp][8 + tig];
                u32 bl1 = sB[comp][8 + tig + 4];
                float2 cc = sC2[l * 32 + 4 * nt + tig];

                float acc0 = 0.f, acc1 = 0.f, acc2 = 0.f, acc3 = 0.f;
                mma16816(acc0, acc1, acc2, acc3, ah0, ah1, ah2, ah3, bh0, bh1);
                mma16816(acc0, acc1, acc2, acc3, ah0, ah1, ah2, ah3, bl0, bl1);
                mma16816(acc0, acc1, acc2, acc3, al0, al1, al2, al3, bh0, bh1);

                // ---- proven packed epilogue on (acc0,acc1), (acc2,acc3) ----
#pragma unroll
                for (int rr = 0; rr < 2; rr++) {
                    float dot0 = (rr == 0) ? acc0 : acc2;
                    float dot1 = (rr == 0) ? acc1 : acc3;
                    float a0 = fminf(fabsf(dot0), CLIP_);
                    float a1 = fminf(fabsf(dot1), CLIP_);
                    u64 pa = pack2(a0, a1);
                    u64 p = fma2(P7, pa, P6);
                    p = fma2(p, pa, P5);
                    p = fma2(p, pa, P4);
                    p = fma2(p, pa, P3);
                    p = fma2(p, pa, P2);
                    p = fma2(p, pa, P1);
                    p = fma2(p, pa, P0);
                    float p0, p1;
                    unpack2(p, p0, p1);
                    float dp0 = fast_sqrt(1.0f - a0) * p0;
                    float dp1 = fast_sqrt(1.0f - a1) * p1;
                    float c0 = copysignf(HALF_PI_ - dp0, dot0);
                    float c1 = copysignf(HALF_PI_ - dp1, dot1);
                    float arg0 = fmaf(fmaf(C1_, c0, Bc), c0, cc.x);
                    float arg1 = fmaf(fmaf(C1_, c1, Bc), c1, cc.y);
                    float e = fast_ex2(arg0) + fast_ex2(arg1);
                    if (rr == 0) sum0 += e; else sum1 += e;
                }
            }

            sum0 += __shfl_xor_sync(0xFFFFFFFFu, sum0, 1);
            sum0 += __shfl_xor_sync(0xFFFFFFFFu, sum0, 2);
            sum1 += __shfl_xor_sync(0xFFFFFFFFu, sum1, 1);
            sum1 += __shfl_xor_sync(0xFFFFFFFFu, sum1, 2);

            float w = sWV[l];
            float mc0 = LN2_TENTH * fast_lg2(sum0);
            float mc1 = LN2_TENTH * fast_lg2(sum1);
            F0 = fmaf(w, fmaxf(F0, 0.f), (1.0f - w) * mc0);
            F1 = fmaf(w, fmaxf(F1, 0.f), (1.0f - w) * mc1);
        }

        // ---- store this m-tile: lane tig==0 of each quad writes 2 points ----
        if (tig == 0) {
            int p0 = blockIdx.x * TILE_M + wid * 32 + mt * 16 + gid;
            if (p0 < n_total)
                out[p0] = 0.1f * log1pf(fast_ex2(C2SCALE_ * F0));
            int p1 = p0 + 8;
            if (p1 < n_total)
                out[p1] = 0.1f * log1pf(fast_ex2(C2SCALE_ * F1));
        }
    }
}

extern "C" void kernel_launch(void* const* d_in, const int* in_sizes, int n_in,
                              void* d_out, int out_size) {
    const float* xs     = (const float*)d_in[0];
    const float* mus    = (const float*)d_in[1];
    const float* alphas = (const float*)d_in[2];
    const float* ws     = (const float*)d_in[3];
    float* out = (float*)d_out;

    int n_total = in_sizes[0] / DD;

    prep_kernel<<<1, LL * KK>>>(mus, alphas, ws);
    int blocks = (n_total + TILE_M - 1) / TILE_M;
    main_kernel<<<blocks, BLOCK>>>(xs, out, n_total);
}

// round 13
// speedup vs baseline: 1.0974x; 1.0974x over previous
#include <cuda_runtime.h>
#include <cuda_bf16.h>
#include <cstdint>

#define DD 16
#define LL 6
#define KK 64
#define BLOCK 256
#define TILE_M 256

typedef unsigned long long u64;
typedef unsigned int u32;

#define C1_        (-7.2134752044448169f)   /* -5 * log2(e)          */
#define C2SCALE_   (-14.426950408889634f)   /* -10 * log2(e)         */
#define PI_        3.14159265358979323846f
#define HALF_PI_   1.5707963267948966f
#define LN2_TENTH  0.069314718055994531f    /* 0.1 * ln(2)           */
#define CLIP_      0.99999994f              /* fp32(1.0 - 1e-7)      */

// B operand, lane-permuted: [384 comps][16 u32]; word 4*t+j = lane t's uint4
// = (mh_t, mh_{t+4}, ml_t, ml_{t+4})  -> one LDS.128 per lane per component-tile
__device__ u32   g_B[LL * KK][16];
__device__ float g_c2p[LL * KK];   // folded: C2SCALE*alpha + C1*(pi/2)^2
__device__ float g_wv[LL];

__device__ __forceinline__ u32 pack_bf16x2(float a, float b) {
    __nv_bfloat162 h = __floats2bfloat162_rn(a, b);
    return *reinterpret_cast<u32*>(&h);
}

// ------------------------------------------------------------------ prep
__global__ void prep_kernel(const float* __restrict__ mus,
                            const float* __restrict__ alphas,
                            const float* __restrict__ ws) {
    int tid = threadIdx.x;
    if (tid < LL) {
        float w = ws[tid];
        g_wv[tid] = expf(-w * w);
    }
    if (tid >= LL * KK) return;
    int l = tid >> 6;
    int k = tid & 63;
    const float* m = mus + l * DD * KK + k;   // [L, D, K]
    float v[DD];
    float s = 0.f;
#pragma unroll
    for (int d = 0; d < DD; d++) {
        v[d] = m[d * KK];
        s += v[d] * v[d];
    }
    float inv = 1.0f / sqrtf(s);
#pragma unroll
    for (int d = 0; d < DD; d++) v[d] *= inv;
    u32 mh[8], ml[8];
#pragma unroll
    for (int i = 0; i < 8; i++) {
        float a = v[2 * i], b = v[2 * i + 1];
        __nv_bfloat162 hb = __floats2bfloat162_rn(a, b);
        float ra = a - __bfloat162float(hb.x);
        float rb = b - __bfloat162float(hb.y);
        mh[i] = *reinterpret_cast<u32*>(&hb);
        ml[i] = pack_bf16x2(ra, rb);
    }
    // permuted store: lane t's uint4 = (mh[t], mh[t+4], ml[t], ml[t+4])
#pragma unroll
    for (int t = 0; t < 4; t++) {
        g_B[tid][4 * t + 0] = mh[t];
        g_B[tid][4 * t + 1] = mh[t + 4];
        g_B[tid][4 * t + 2] = ml[t];
        g_B[tid][4 * t + 3] = ml[t + 4];
    }
    g_c2p[tid] = C2SCALE_ * alphas[tid] + C1_ * (HALF_PI_ * HALF_PI_);
}

// ---------------------------------------------------------------- helpers
__device__ __forceinline__ float fast_sqrt(float x) {
    float r; asm("sqrt.approx.f32 %0, %1;" : "=f"(r) : "f"(x)); return r;
}
__device__ __forceinline__ float fast_ex2(float x) {
    float r; asm("ex2.approx.f32 %0, %1;" : "=f"(r) : "f"(x)); return r;
}
__device__ __forceinline__ float fast_lg2(float x) {
    float r; asm("lg2.approx.f32 %0, %1;" : "=f"(r) : "f"(x)); return r;
}

// m16n8k16 row.col bf16 -> f32 accumulate (plain PTX, valid on compute_103)
__device__ __forceinline__ void mma16816(float& d0, float& d1, float& d2, float& d3,
                                         u32 a0, u32 a1, u32 a2, u32 a3,
                                         u32 b0, u32 b1) {
    asm volatile(
        "mma.sync.aligned.m16n8k16.row.col.f32.bf16.bf16.f32 "
        "{%0,%1,%2,%3}, {%4,%5,%6,%7}, {%8,%9}, {%0,%1,%2,%3};"
        : "+f"(d0), "+f"(d1), "+f"(d2), "+f"(d3)
        : "r"(a0), "r"(a1), "r"(a2), "r"(a3), "r"(b0), "r"(b1));
}

// scalar deg-3 acos epilogue core (A&S 4.4.45, |eps|<=6.8e-5):
// returns exp2((C1*c + Bc)*c + c2') with c = copysign(pi/2 - acos(|dot|), dot)
__device__ __forceinline__ float ep_term(float dot, float c2, float Bc) {
    float a = fminf(fabsf(dot), CLIP_);
    float p = fmaf(fmaf(fmaf(-0.0187293f, a, 0.0742610f), a, -0.2121144f),
                   a, 1.5707288f);
    float dp = fast_sqrt(1.0f - a) * p;
    float c = copysignf(HALF_PI_ - dp, dot);
    float arg = fmaf(fmaf(C1_, c, Bc), c, c2);
    return fast_ex2(arg);
}

// ------------------------------------------------------------------ main
__global__ __launch_bounds__(BLOCK, 5)
void main_kernel(const float* __restrict__ xs,
                 float* __restrict__ out,
                 int n_total) {
    __shared__ u32    sA[TILE_M][17];        // 17.0 KB: [xh(8)|xl(8)] + pad
    __shared__ uint4  sB4[LL * KK * 4];      // 24.0 KB permuted B (uint4/lane)
    __shared__ float2 sC2[LL * 32];          // 1.5 KB folded c2' pairs
    __shared__ float  sWV[LL];

    const int tid = threadIdx.x;
    {
        const float2* gc = reinterpret_cast<const float2*>(g_c2p);
        for (int i = tid; i < LL * 32; i += BLOCK) sC2[i] = gc[i];
        if (tid < LL) sWV[tid] = g_wv[tid];
    }

    // ---- copy permuted B table to smem (uint4 straight copy) ----
    {
        const uint4* gb = reinterpret_cast<const uint4*>(&g_B[0][0]);
#pragma unroll
        for (int i = tid; i < LL * KK * 4; i += BLOCK) sB4[i] = gb[i];
    }

    // ---- build A rows: thread tid owns point blockIdx*256 + tid ----
    int n0 = blockIdx.x * TILE_M + tid;
    int n_c = (n0 < n_total) ? n0 : (n_total - 1);
    {
        const float4* xv = reinterpret_cast<const float4*>(xs + (size_t)n_c * DD);
        float4 v0 = xv[0], v1 = xv[1], v2 = xv[2], v3 = xv[3];
        float x[16] = {v0.x, v0.y, v0.z, v0.w, v1.x, v1.y, v1.z, v1.w,
                       v2.x, v2.y, v2.z, v2.w, v3.x, v3.y, v3.z, v3.w};
#pragma unroll
        for (int i = 0; i < 8; i++) {
            float a = x[2 * i], b = x[2 * i + 1];
            __nv_bfloat162 hb = __floats2bfloat162_rn(a, b);
            float ra = a - __bfloat162float(hb.x);
            float rb = b - __bfloat162float(hb.y);
            sA[tid][i]     = *reinterpret_cast<u32*>(&hb);
            sA[tid][8 + i] = pack_bf16x2(ra, rb);
        }
    }
    __syncthreads();

    const int wid = tid >> 5;
    const int lane = tid & 31;
    const int gid = lane >> 2;   // quad row id 0..7 (also component-in-tile)
    const int tig = lane & 3;    // thread-in-group
    const float Bc = -(C1_) * PI_;

    // mt OUTER loop (reg diet); nt fully unrolled inside
#pragma unroll 1
    for (int mt = 0; mt < 2; mt++) {
        const int r0 = wid * 32 + mt * 16 + gid;
        u32 ah0 = sA[r0][tig],     ah1 = sA[r0 + 8][tig];
        u32 ah2 = sA[r0][tig + 4], ah3 = sA[r0 + 8][tig + 4];
        u32 al0 = sA[r0][8 + tig],     al1 = sA[r0 + 8][8 + tig];
        u32 al2 = sA[r0][8 + tig + 4], al3 = sA[r0 + 8][8 + tig + 4];

        float F0 = 0.f, F1 = 0.f;
#pragma unroll 1
        for (int l = 0; l < LL; l++) {
            // base pointers for this layer: immediate offsets per nt
            const uint4*  bp = sB4 + (l * 64 + gid) * 4 + tig;
            const float2* cp = sC2 + l * 32 + tig;
            float sum0 = 0.f, sum1 = 0.f;
#pragma unroll
            for (int nt = 0; nt < 8; nt++) {
                uint4  bv = bp[nt * 32];     // (bh0, bh1, bl0, bl1): 1 LDS.128
                float2 cc = cp[nt * 4];

                float acc0 = 0.f, acc1 = 0.f, acc2 = 0.f, acc3 = 0.f;
                mma16816(acc0, acc1, acc2, acc3, ah0, ah1, ah2, ah3, bv.x, bv.y);
                mma16816(acc0, acc1, acc2, acc3, ah0, ah1, ah2, ah3, bv.z, bv.w);
                mma16816(acc0, acc1, acc2, acc3, al0, al1, al2, al3, bv.x, bv.y);

                sum0 += ep_term(acc0, cc.x, Bc);
                sum0 += ep_term(acc1, cc.y, Bc);
                sum1 += ep_term(acc2, cc.x, Bc);
                sum1 += ep_term(acc3, cc.y, Bc);
            }

            sum0 += __shfl_xor_sync(0xFFFFFFFFu, sum0, 1);
            sum0 += __shfl_xor_sync(0xFFFFFFFFu, sum0, 2);
            sum1 += __shfl_xor_sync(0xFFFFFFFFu, sum1, 1);
            sum1 += __shfl_xor_sync(0xFFFFFFFFu, sum1, 2);

            float w = sWV[l];
            float mc0 = LN2_TENTH * fast_lg2(sum0);
            float mc1 = LN2_TENTH * fast_lg2(sum1);
            F0 = fmaf(w, fmaxf(F0, 0.f), (1.0f - w) * mc0);
            F1 = fmaf(w, fmaxf(F1, 0.f), (1.0f - w) * mc1);
        }

        // ---- store this m-tile: lane tig==0 of each quad writes 2 points ----
        if (tig == 0) {
            int p0 = blockIdx.x * TILE_M + wid * 32 + mt * 16 + gid;
            if (p0 < n_total)
                out[p0] = 0.1f * log1pf(fast_ex2(C2SCALE_ * F0));
            int p1 = p0 + 8;
            if (p1 < n_total)
                out[p1] = 0.1f * log1pf(fast_ex2(C2SCALE_ * F1));
        }
    }
}

extern "C" void kernel_launch(void* const* d_in, const int* in_sizes, int n_in,
                              void* d_out, int out_size) {
    const float* xs     = (const float*)d_in[0];
    const float* mus    = (const float*)d_in[1];
    const float* alphas = (const float*)d_in[2];
    const float* ws     = (const float*)d_in[3];
    float* out = (float*)d_out;

    int n_total = in_sizes[0] / DD;

    prep_kernel<<<1, LL * KK>>>(mus, alphas, ws);
    int blocks = (n_total + TILE_M - 1) / TILE_M;
    main_kernel<<<blocks, BLOCK>>>(xs, out, n_total);
}